// round 17
// baseline (speedup 1.0000x reference)
#include <cuda_runtime.h>
#include <cuda_bf16.h>
#include <math.h>
#include <stdint.h>

#define BB 256
#define NN 256
#define DD 256
#define UU 256

typedef unsigned long long ull;

// ---------------------------------------------------------------------------
// Scratch (static __device__ arrays; no allocations allowed)
// ---------------------------------------------------------------------------
__device__ float g_fiou[(size_t)BB * NN * 1024];  // [b][n][1024]: 0..255=f, 256..511=i, 512..767=o, 768..1023=u
__device__ float g_csh[(size_t)BB * NN * UU];     // child-sum of hidden
__device__ float g_gcs[(size_t)BB * NN * UU];     // gated child cell sum
__device__ float g_out[BB * UU];                  // out for current step
__device__ float g_mem[BB * UU];                  // mem for current step

// Pre-converted bf16 hi/lo operands for the precompute GEMM
__device__ __nv_bfloat16 g_Xh[(size_t)BB * NN * DD];
__device__ __nv_bfloat16 g_Xl[(size_t)BB * NN * DD];
__device__ __nv_bfloat16 g_Wth[1024 * 256];   // W transposed [n][k], hi
__device__ __nv_bfloat16 g_Wtl[1024 * 256];   // lo

// Fast transcendentals: __expf rel-err ~2^-21, far inside the 1e-3 budget.
__device__ __forceinline__ float sigm_(float x) {
    return __fdividef(1.f, 1.f + __expf(-x));
}
__device__ __forceinline__ float tanh_(float x) {
    x = fminf(fmaxf(x, -15.f), 15.f);
    float e = __expf(2.f * x);
    return __fdividef(e - 1.f, e + 1.f);
}

// Hardware cluster barrier: synchronizes all threads of the 8-CTA cluster.
// arrive has release, wait has acquire semantics (cluster scope covers the
// L2-visible global writes our __ldcg readers consume).
__device__ __forceinline__ void csync() {
    asm volatile("barrier.cluster.arrive.aligned;" ::: "memory");
    asm volatile("barrier.cluster.wait.aligned;" ::: "memory");
}

// ---------------------------------------------------------------------------
// Zero csh, gcs, hs (output is poisoned before every timed replay)
// ---------------------------------------------------------------------------
__global__ void k_zero(float4* __restrict__ hs4) {
    const size_t n4 = ((size_t)BB * NN * UU) / 4;
    float4 z = make_float4(0.f, 0.f, 0.f, 0.f);
    float4* c4 = (float4*)g_csh;
    float4* g4 = (float4*)g_gcs;
    for (size_t i = (size_t)blockIdx.x * blockDim.x + threadIdx.x; i < n4;
         i += (size_t)gridDim.x * blockDim.x) {
        c4[i] = z; g4[i] = z; hs4[i] = z;
    }
}

// ---------------------------------------------------------------------------
// mma.sync helpers (layout recipe validated by R13/R14/R15)
// ---------------------------------------------------------------------------
__device__ __forceinline__ uint32_t smem_u32(const void* p) {
    uint32_t a;
    asm("{ .reg .u64 t; cvta.to.shared.u64 t, %1; cvt.u32.u64 %0, t; }"
        : "=r"(a) : "l"(p));
    return a;
}
__device__ __forceinline__ uint32_t bf2(float x, float y) {
    uint32_t r;
    asm("cvt.rn.bf16x2.f32 %0, %1, %2;" : "=r"(r) : "f"(y), "f"(x));
    return r;
}
__device__ __forceinline__ void ldm_x4(uint32_t (&r)[4], uint32_t addr) {
    asm volatile("ldmatrix.sync.aligned.m8n8.x4.shared.b16 {%0,%1,%2,%3}, [%4];"
        : "=r"(r[0]), "=r"(r[1]), "=r"(r[2]), "=r"(r[3]) : "r"(addr));
}
__device__ __forceinline__ void mma_bf16(float (&d)[4], const uint32_t (&a)[4],
                                         uint32_t b0, uint32_t b1) {
    asm volatile(
        "mma.sync.aligned.m16n8k16.row.col.f32.bf16.bf16.f32 "
        "{%0,%1,%2,%3}, {%4,%5,%6,%7}, {%8,%9}, {%0,%1,%2,%3};"
        : "+f"(d[0]), "+f"(d[1]), "+f"(d[2]), "+f"(d[3])
        : "r"(a[0]), "r"(a[1]), "r"(a[2]), "r"(a[3]), "r"(b0), "r"(b1));
}

// ---------------------------------------------------------------------------
// One-time operand conversion: X -> bf16 hi/lo; W -> transposed bf16 hi/lo
// ---------------------------------------------------------------------------
__global__ void k_convX(const float4* __restrict__ X4) {
    size_t i = (size_t)blockIdx.x * blockDim.x + threadIdx.x;
    float4 v = X4[i];
    float hx = __bfloat162float(__float2bfloat16(v.x));
    float hy = __bfloat162float(__float2bfloat16(v.y));
    float hz = __bfloat162float(__float2bfloat16(v.z));
    float hw = __bfloat162float(__float2bfloat16(v.w));
    ((uint2*)g_Xh)[i] = make_uint2(bf2(v.x, v.y), bf2(v.z, v.w));
    ((uint2*)g_Xl)[i] = make_uint2(bf2(v.x - hx, v.y - hy), bf2(v.z - hz, v.w - hw));
}

__global__ void k_convW(const float* __restrict__ W) {
    int i = blockIdx.x * 256 + threadIdx.x;
    int n = i >> 6, q = i & 63;
    float w0 = W[(size_t)(q * 4 + 0) * 1024 + n];
    float w1 = W[(size_t)(q * 4 + 1) * 1024 + n];
    float w2 = W[(size_t)(q * 4 + 2) * 1024 + n];
    float w3 = W[(size_t)(q * 4 + 3) * 1024 + n];
    float h0 = __bfloat162float(__float2bfloat16(w0));
    float h1 = __bfloat162float(__float2bfloat16(w1));
    float h2 = __bfloat162float(__float2bfloat16(w2));
    float h3 = __bfloat162float(__float2bfloat16(w3));
    ((uint2*)g_Wth)[i] = make_uint2(bf2(w0, w1), bf2(w2, w3));
    ((uint2*)g_Wtl)[i] = make_uint2(bf2(w0 - h0, w1 - h1), bf2(w2 - h2, w3 - h3));
}

// ===========================================================================
// Tensor-core precompute, double-buffered smem staging (ping-pong 2 x 80KB).
// ===========================================================================
#define PC_AH 0
#define PC_AL 20480
#define PC_BH 40960
#define PC_BL 61440
#define PC_BUF 81920
#define PC_SMEM (2 * PC_BUF)   // 163840 B

__global__ void __launch_bounds__(256, 1) k_precompute_mma(
    const float* __restrict__ bias)
{
    extern __shared__ __align__(16) char smc[];
    const uint32_t sb = smem_u32(smc);
    const int tid  = threadIdx.x;
    const int lane = tid & 31;
    const int w    = tid >> 5;
    const int wm   = w >> 2;
    const int wn   = w & 3;
    const int N0   = blockIdx.x * 128;
    const int M0   = blockIdx.y * 128;

    float acc[4][4][4];
#pragma unroll
    for (int mi = 0; mi < 4; ++mi)
#pragma unroll
        for (int ni = 0; ni < 4; ++ni)
#pragma unroll
            for (int q = 0; q < 4; ++q) acc[mi][ni][q] = 0.f;

    auto stage = [&](int bsel, int kc) {
        char* base = smc + bsel * PC_BUF;
#pragma unroll
        for (int it = 0; it < 4; ++it) {
            int i = tid + it * 256;
            int r = i >> 3, q = i & 7;
            size_t src = (size_t)(M0 + r) * DD + kc + q * 8;
            uint32_t off = (uint32_t)(r * 160 + q * 16);
            *(uint4*)(base + PC_AH + off) = *(const uint4*)&g_Xh[src];
            *(uint4*)(base + PC_AL + off) = *(const uint4*)&g_Xl[src];
        }
#pragma unroll
        for (int it = 0; it < 4; ++it) {
            int i = tid + it * 256;
            int n = i >> 3, q = i & 7;
            size_t src = (size_t)(N0 + n) * 256 + kc + q * 8;
            uint32_t off = (uint32_t)(n * 160 + q * 16);
            *(uint4*)(base + PC_BH + off) = *(const uint4*)&g_Wth[src];
            *(uint4*)(base + PC_BL + off) = *(const uint4*)&g_Wtl[src];
        }
    };

    stage(0, 0);
    __syncthreads();

    for (int kc2 = 0; kc2 < 4; ++kc2) {
        const int cur = kc2 & 1;
        if (kc2 < 3) stage(cur ^ 1, (kc2 + 1) * 64);  // overlap with mma below
        const uint32_t bb = sb + cur * PC_BUF;

#pragma unroll
        for (int kk = 0; kk < 4; ++kk) {
            const uint32_t kb = (uint32_t)(kk * 32 + (lane >> 4) * 16);
            uint32_t ah[4][4], al[4][4];
#pragma unroll
            for (int mi = 0; mi < 4; ++mi) {
                uint32_t ro = (uint32_t)((wm * 64 + mi * 16 + (lane & 15)) * 160) + kb;
                ldm_x4(ah[mi], bb + PC_AH + ro);
                ldm_x4(al[mi], bb + PC_AL + ro);
            }
            uint32_t bh[2][4], bl[2][4];
#pragma unroll
            for (int nj = 0; nj < 2; ++nj) {
                uint32_t ro = (uint32_t)((wn * 32 + nj * 16 + (lane & 15)) * 160) + kb;
                ldm_x4(bh[nj], bb + PC_BH + ro);
                ldm_x4(bl[nj], bb + PC_BL + ro);
            }
#pragma unroll
            for (int mi = 0; mi < 4; ++mi)
#pragma unroll
                for (int ni = 0; ni < 4; ++ni) {
                    int nj = ni >> 1, sel = ni & 1;
                    uint32_t bh0 = bh[nj][sel], bh1 = bh[nj][sel + 2];
                    mma_bf16(acc[mi][ni], ah[mi], bh0, bh1);
                    mma_bf16(acc[mi][ni], al[mi], bh0, bh1);
                    mma_bf16(acc[mi][ni], ah[mi], bl[nj][sel], bl[nj][sel + 2]);
                }
        }
        __syncthreads();
    }

    const int gr = lane >> 2, tg = lane & 3;
#pragma unroll
    for (int ni = 0; ni < 4; ++ni) {
        int col = N0 + wn * 32 + ni * 8 + tg * 2;
        float2 bv = *(const float2*)&bias[col];
#pragma unroll
        for (int mi = 0; mi < 4; ++mi) {
            int row = M0 + wm * 64 + mi * 16 + gr;
            *(float2*)&g_fiou[(size_t)row * 1024 + col] =
                make_float2(acc[mi][ni][0] + bv.x, acc[mi][ni][1] + bv.y);
            *(float2*)&g_fiou[(size_t)(row + 8) * 1024 + col] =
                make_float2(acc[mi][ni][2] + bv.x, acc[mi][ni][3] + bv.y);
        }
    }
}

// ===========================================================================
// Persistent recurrence (R15 logic; group barriers -> HW cluster barriers)
// ===========================================================================
#define RC_WtH 0
#define RC_WtL 50688
#define RC_HfH 101376
#define RC_HfL 118272
#define RC_AsH 135168
#define RC_AsL 143616
#define RC_OuH 152064
#define RC_OuL 160512
#define RC_OuF 168960
#define RC_RED 185600
#define RC_SMEM 211200

__global__ void __launch_bounds__(256, 1) __cluster_dims__(8, 1, 1) k_recur(
    const int*   __restrict__ parents,
    const int*   __restrict__ post,
    const float* __restrict__ hf,
    const float* __restrict__ hiou,
    float*       __restrict__ hs)
{
    extern __shared__ __align__(16) char smc[];
    const uint32_t sb = smem_u32(smc);
    float* red = (float*)(smc + RC_RED);

    const int c    = blockIdx.x;
    const int cig  = c & 7;        // == cluster rank
    const int grp  = c >> 3;
    const int tid  = threadIdx.x;
    const int lane = tid & 31;
    const int w    = tid >> 5;
    const int tx   = tid & 15;
    const int ty   = tid >> 4;

    const int bG0 = grp * 16;
    const int uA0 = cig * 32;
    const int cC0 = cig * 32;

    // ---- one-time weight staging: transposed, bf16 hi/lo ----
    for (int e = tid; e < 24576; e += 256) {
        int col = e % 96, k = e / 96;
        int gate = col >> 5, unit = col & 31;
        float v = hiou[(size_t)k * 768 + gate * 256 + uA0 + unit];
        __nv_bfloat16 h = __float2bfloat16(v);
        *(__nv_bfloat16*)(smc + RC_WtH + col * 528 + k * 2) = h;
        *(__nv_bfloat16*)(smc + RC_WtL + col * 528 + k * 2) =
            __float2bfloat16(v - __bfloat162float(h));
    }
    for (int e = tid; e < 8192; e += 256) {
        int col = e & 31, k = e >> 5;
        float v = hf[(size_t)k * 256 + cC0 + col];
        __nv_bfloat16 h = __float2bfloat16(v);
        *(__nv_bfloat16*)(smc + RC_HfH + col * 528 + k * 2) = h;
        *(__nv_bfloat16*)(smc + RC_HfL + col * 528 + k * 2) =
            __float2bfloat16(v - __bfloat162float(h));
    }
    __syncthreads();

    const int gr  = lane >> 2;
    const int tg2 = (lane & 3) * 2;

    for (int t = 0; t < NN; ++t) {
        // ================= Phase A: GEMM1 (mma) + gates =================
        {
            const int bA = bG0 + ty;
            const int u2 = uA0 + tx * 2;
            int poA = post[bA * NN + t];
            int tgA = poA < 0 ? 0 : poA;
            size_t fb = ((size_t)bA * NN + tgA) * 1024 + u2;
            float2 fi = *(const float2*)&g_fiou[fb + 256];
            float2 fo = *(const float2*)&g_fiou[fb + 512];
            float2 fu = *(const float2*)&g_fiou[fb + 768];
            float2 gc = __ldcg((const float2*)&g_gcs[((size_t)bA * NN + tgA) * UU + u2]);

            {
                int r = tid >> 4, q0 = tid & 15;
                int po = post[(bG0 + r) * NN + t];
                int tg = po < 0 ? 0 : po;
                const float4* src =
                    (const float4*)&g_csh[(((size_t)(bG0 + r)) * NN + tg) * UU];
#pragma unroll
                for (int j = 0; j < 4; ++j) {
                    float4 v = __ldcg(&src[q0 + j * 16]);
                    float hx = __bfloat162float(__float2bfloat16(v.x));
                    float hy = __bfloat162float(__float2bfloat16(v.y));
                    float hz = __bfloat162float(__float2bfloat16(v.z));
                    float hw = __bfloat162float(__float2bfloat16(v.w));
                    uint32_t off = (uint32_t)(r * 528 + (q0 + j * 16) * 8);
                    *(uint2*)(smc + RC_AsH + off) =
                        make_uint2(bf2(v.x, v.y), bf2(v.z, v.w));
                    *(uint2*)(smc + RC_AsL + off) =
                        make_uint2(bf2(v.x - hx, v.y - hy), bf2(v.z - hz, v.w - hw));
                }
            }
            __syncthreads();

            const int ks = w & 3;
            const int ch = w >> 2;
            float acc[6][4];
#pragma unroll
            for (int nt = 0; nt < 6; ++nt)
#pragma unroll
                for (int q = 0; q < 4; ++q) acc[nt][q] = 0.f;

#pragma unroll
            for (int kk = 0; kk < 4; ++kk) {
                const uint32_t kb = (uint32_t)((ks * 64 + kk * 16) * 2 + (lane >> 4) * 16);
                uint32_t ah[4], al[4];
                uint32_t aaddr = sb + RC_AsH + (uint32_t)((lane & 15) * 528) + kb;
                ldm_x4(ah, aaddr);
                ldm_x4(al, aaddr + (RC_AsL - RC_AsH));
#pragma unroll
                for (int nb = 0; nb < 3; ++nb) {
                    uint32_t baddr = sb + RC_WtH +
                        (uint32_t)((ch * 48 + nb * 16 + (lane & 15)) * 528) + kb;
                    uint32_t bh[4], bl[4];
                    ldm_x4(bh, baddr);
                    ldm_x4(bl, baddr + (RC_WtL - RC_WtH));
#pragma unroll
                    for (int sel = 0; sel < 2; ++sel) {
                        int nt = nb * 2 + sel;
                        mma_bf16(acc[nt], ah, bh[sel], bh[sel + 2]);
                        mma_bf16(acc[nt], al, bh[sel], bh[sel + 2]);
                        mma_bf16(acc[nt], ah, bl[sel], bl[sel + 2]);
                    }
                }
            }
#pragma unroll
            for (int nt = 0; nt < 6; ++nt) {
                int col = ch * 48 + nt * 8 + tg2;
                *(float2*)&red[(ks * 16 + gr) * 100 + col] =
                    make_float2(acc[nt][0], acc[nt][1]);
                *(float2*)&red[(ks * 16 + gr + 8) * 100 + col] =
                    make_float2(acc[nt][2], acc[nt][3]);
            }
            __syncthreads();

            float memv[2], outv[2];
#pragma unroll
            for (int j = 0; j < 2; ++j) {
                int u = tx * 2 + j;
                float aI = 0.f, aO = 0.f, aU = 0.f;
#pragma unroll
                for (int s = 0; s < 4; ++s) {
                    int rb = (s * 16 + ty) * 100;
                    aI += red[rb + u];
                    aO += red[rb + 32 + u];
                    aU += red[rb + 64 + u];
                }
                float fiv = j ? fi.y : fi.x;
                float fov = j ? fo.y : fo.x;
                float fuv = j ? fu.y : fu.x;
                float gcv = j ? gc.y : gc.x;
                memv[j] = sigm_(aI + fiv) * tanh_(aU + fuv) + gcv;
                outv[j] = sigm_(aO + fov) * tanh_(memv[j]);
            }
            *(float2*)&g_out[bA * UU + u2] = make_float2(outv[0], outv[1]);
            *(float2*)&g_mem[bA * UU + u2] = make_float2(memv[0], memv[1]);
        }
        csync();

        // ================= Phase C: GEMM2 (mma) + gated scatter =================
        {
            const int b  = bG0 + ty;
            const int cc = cC0 + tx * 2;
            int po = post[b * NN + t];
            int om = po >= 0;
            int tg = om ? po : 0;
            int pr = parents[b * NN + tg];
            int pm = om && (pr >= 0);
            int pa = pr < 0 ? 0 : pr;
            float2 fx    = *(const float2*)&g_fiou[((size_t)b * NN + pa) * 1024 + cc];
            float2 csh_o = *(const float2*)&g_csh[((size_t)b * NN + pa) * UU + cc];
            float2 gcs_o = *(const float2*)&g_gcs[((size_t)b * NN + pa) * UU + cc];
            float2 mm    = __ldcg((const float2*)&g_mem[b * UU + cc]);

            {
                int r = tid >> 4, q0 = tid & 15;
                const float4* src = (const float4*)&g_out[(bG0 + r) * UU];
#pragma unroll
                for (int j = 0; j < 4; ++j) {
                    float4 v = __ldcg(&src[q0 + j * 16]);
                    int q = q0 + j * 16;
                    *(float4*)(smc + RC_OuF + r * 1040 + q * 16) = v;
                    float hx = __bfloat162float(__float2bfloat16(v.x));
                    float hy = __bfloat162float(__float2bfloat16(v.y));
                    float hz = __bfloat162float(__float2bfloat16(v.z));
                    float hw = __bfloat162float(__float2bfloat16(v.w));
                    uint32_t off = (uint32_t)(r * 528 + q * 8);
                    *(uint2*)(smc + RC_OuH + off) =
                        make_uint2(bf2(v.x, v.y), bf2(v.z, v.w));
                    *(uint2*)(smc + RC_OuL + off) =
                        make_uint2(bf2(v.x - hx, v.y - hy), bf2(v.z - hz, v.w - hw));
                }
            }
            __syncthreads();

            float accC[4][4];
#pragma unroll
            for (int nt = 0; nt < 4; ++nt)
#pragma unroll
                for (int q = 0; q < 4; ++q) accC[nt][q] = 0.f;

#pragma unroll
            for (int kk = 0; kk < 2; ++kk) {
                const uint32_t kb = (uint32_t)((w * 32 + kk * 16) * 2 + (lane >> 4) * 16);
                uint32_t ah[4], al[4];
                uint32_t aaddr = sb + RC_OuH + (uint32_t)((lane & 15) * 528) + kb;
                ldm_x4(ah, aaddr);
                ldm_x4(al, aaddr + (RC_OuL - RC_OuH));
#pragma unroll
                for (int nb = 0; nb < 2; ++nb) {
                    uint32_t baddr = sb + RC_HfH +
                        (uint32_t)((nb * 16 + (lane & 15)) * 528) + kb;
                    uint32_t bh[4], bl[4];
                    ldm_x4(bh, baddr);
                    ldm_x4(bl, baddr + (RC_HfL - RC_HfH));
#pragma unroll
                    for (int sel = 0; sel < 2; ++sel) {
                        int nt = nb * 2 + sel;
                        mma_bf16(accC[nt], ah, bh[sel], bh[sel + 2]);
                        mma_bf16(accC[nt], al, bh[sel], bh[sel + 2]);
                        mma_bf16(accC[nt], ah, bl[sel], bl[sel + 2]);
                    }
                }
            }
#pragma unroll
            for (int nt = 0; nt < 4; ++nt) {
                int col = nt * 8 + tg2;
                *(float2*)&red[(w * 16 + gr) * 36 + col] =
                    make_float2(accC[nt][0], accC[nt][1]);
                *(float2*)&red[(w * 16 + gr + 8) * 36 + col] =
                    make_float2(accC[nt][2], accC[nt][3]);
            }
            __syncthreads();

            float accv[2];
#pragma unroll
            for (int j = 0; j < 2; ++j) {
                int cl = tx * 2 + j;
                float s = 0.f;
#pragma unroll
                for (int ks = 0; ks < 8; ++ks)
                    s += red[(ks * 16 + ty) * 36 + cl];
                accv[j] = s;
            }
            float2 outp = *(const float2*)(smc + RC_OuF + ty * 1040 + cc * 4);
            float gx = sigm_(accv[0] + fx.x) * mm.x;
            float gy = sigm_(accv[1] + fx.y) * mm.y;
            if (pm) {
                *(float2*)&g_csh[((size_t)b * NN + pa) * UU + cc] =
                    make_float2(csh_o.x + outp.x, csh_o.y + outp.y);
                *(float2*)&g_gcs[((size_t)b * NN + pa) * UU + cc] =
                    make_float2(gcs_o.x + gx, gcs_o.y + gy);
            }
            if (om) {
                *(float2*)&hs[((size_t)b * NN + tg) * UU + cc] = outp;
            }
        }
        csync();
    }
}

// ---------------------------------------------------------------------------
// Launch: 5 graph nodes.
// ---------------------------------------------------------------------------
extern "C" void kernel_launch(void* const* d_in, const int* in_sizes, int n_in,
                              void* d_out, int out_size)
{
    const float* inputs  = (const float*)d_in[0];
    const int*   parents = (const int*)  d_in[1];
    const int*   post    = (const int*)  d_in[2];
    const float* xf      = (const float*)d_in[3];
    const float* hfk     = (const float*)d_in[4];
    const float* hiou    = (const float*)d_in[5];
    const float* bias    = (const float*)d_in[6];
    float* hs = (float*)d_out;

    (void)in_sizes; (void)n_in; (void)out_size;

    static int smem_set = 0;
    if (!smem_set) {
        cudaFuncSetAttribute(k_recur, cudaFuncAttributeMaxDynamicSharedMemorySize,
                             RC_SMEM);
        cudaFuncSetAttribute(k_precompute_mma,
                             cudaFuncAttributeMaxDynamicSharedMemorySize, PC_SMEM);
        smem_set = 1;
    }

    k_zero<<<2048, 256>>>((float4*)hs);
    k_convX<<<16384, 256>>>((const float4*)inputs);
    k_convW<<<256, 256>>>(xf);
    k_precompute_mma<<<dim3(8, 512), 256, PC_SMEM>>>(bias);
    k_recur<<<128, 256, RC_SMEM>>>(parents, post, hfk, hiou, hs);
}